// round 11
// baseline (speedup 1.0000x reference)
#include <cuda_runtime.h>
#include <cuda_bf16.h>
#include <math.h>
#include <stdint.h>

#define BB 2
#define NROI 625
#define NTOT 1250
#define CC 512
#define DD 25088            // 512*49
#define H1 200
#define H2 100
#define KC 17
#define NKEY 2402
#define TOTKEY 4804
#define MAXROWS 1250
#define KSPLIT 98
#define KCHUNK 256
#define NSLAB 8             // KCHUNK/32
#define NBLK 296
#define NTHR 256
#define GM_BM 64
#define SASTR 36

// ---------------- scratch ----------------
__device__ float g_A[(size_t)MAXROWS * DD];
__device__ float g_P[(size_t)MAXROWS * KSPLIT * H1];   // [row][ks][H1]
__device__ float g_FT[BB * 49 * CC];                   // transposed tf32 feats [b][p][c]
__device__ float g_out85[MAXROWS * 85];
__device__ int   g_keyOfRow[TOTKEY];
__device__ int   g_roiRow[NTOT];
__device__ int   g_M[1];
__device__ unsigned long long g_barcnt[8];   // monotonic epochs; never reset

// ---------------- helpers ----------------
__device__ __forceinline__ float tf32r(float x) {
    uint32_t u;
    asm("cvt.rna.tf32.f32 %0, %1;" : "=r"(u) : "f"(x));
    return __uint_as_float(u);
}
__device__ __forceinline__ void mma_tf32(float& d0, float& d1, float& d2, float& d3,
                                         uint32_t a0, uint32_t a1, uint32_t a2, uint32_t a3,
                                         uint32_t b0, uint32_t b1) {
    asm volatile(
        "mma.sync.aligned.m16n8k8.row.col.f32.tf32.tf32.f32 "
        "{%0,%1,%2,%3}, {%4,%5,%6,%7}, {%8,%9}, {%0,%1,%2,%3};\n"
        : "+f"(d0), "+f"(d1), "+f"(d2), "+f"(d3)
        : "r"(a0), "r"(a1), "r"(a2), "r"(a3), "r"(b0), "r"(b1));
}

// monotonic grid barrier: arrivals via atomicAdd; waiting via plain volatile loads.
__device__ __forceinline__ void grid_barrier(int k) {
    __syncthreads();
    if (threadIdx.x == 0) {
        __threadfence();
        unsigned long long my = atomicAdd(&g_barcnt[k], 1ULL) + 1ULL;
        unsigned long long target = ((my - 1ULL) / NBLK + 1ULL) * NBLK;
        volatile unsigned long long* p = (volatile unsigned long long*)&g_barcnt[k];
        while (*p < target) { __nanosleep(60); }
        __threadfence();
    }
    __syncthreads();
}

// ---------------- the megakernel ----------------
__global__ void __launch_bounds__(NTHR, 2) mega_kernel(
    const float* __restrict__ cf, const float* __restrict__ regcls,
    const float* __restrict__ wan, const float* __restrict__ han,
    const float* __restrict__ xan, const float* __restrict__ yan,
    const float* __restrict__ w1, const float* __restrict__ b1,
    const float* __restrict__ w2, const float* __restrict__ b2,
    const float* __restrict__ w3, const float* __restrict__ b3,
    const float* __restrict__ w4, const float* __restrict__ b4,
    float* __restrict__ out)
{
    __shared__ __align__(16) float sp[GM_BM * SASTR + H1 * SASTR];  // 9504 floats = 38KB
    const int tid = threadIdx.x;
    const int bid = blockIdx.x;
    const int lane = tid & 31, wid = tid >> 5;

    // ================= phase A: g_FT build (spread) + decode/dedup (block 0) =======
    {
        const int NF = BB * CC * 49;   // 50176
        for (int i = bid * NTHR + tid; i < NF; i += NBLK * NTHR) {
            float v = tf32r(cf[i]);    // coalesced read
            int p = i % 49;
            int bc = i / 49;
            int c = bc & 511;
            int b = bc >> 9;
            g_FT[(b * 49 + p) * CC + c] = v;
        }
    }
    if (bid == 0) {
        int* s_used = reinterpret_cast<int*>(sp);
        int* s_key = s_used + TOTKEY;
        int* wsum = s_key + NTOT;   // 8 ints
        for (int i = tid; i < TOTKEY; i += NTHR) s_used[i] = 0;
        __syncthreads();
        for (int idx = tid; idx < NTOT; idx += NTHR) {
            int b = idx / NROI;
            int n = idx % NROI;
            const float* reg = regcls + (size_t)b * 5 * NROI;
            float r0 = reg[n];
            float r1 = reg[NROI + n];
            float r2 = reg[2 * NROI + n];
            float r3 = reg[3 * NROI + n];
            float w = wan[n], h = han[n], xa = xan[n], ya = yan[n];
            float wreg = expf(r2) * w;
            float hreg = expf(r3) * h;
            float xreg = r0 * w + xa;
            float yreg = r1 * h + ya;
            float xis = xreg - wreg * 0.5f;
            float yis = yreg - hreg * 0.5f;
            float xfs = xreg + wreg * 0.5f;
            float yfs = yreg + hreg * 0.5f;
            float c0 = floorf(fmaxf(xis, 0.f));
            float c1 = floorf(fmaxf(yis, 0.f));
            float c2 = fminf(ceilf(xfs), 295.f);
            float c3 = fmaxf(ceilf(yfs), 295.f);   // (sic) max, as in source
            bool on = (xis < 296.f) && (yis < 296.f) && (xfs >= 0.f) && (yfs >= 0.f);
#define CONV_STEP(L) { c0 = fmaxf(c0 - 1.f, 0.f); c1 = fmaxf(c1 - 1.f, 0.f); \
                       c2 = fminf(c2, (float)(L)); c3 = fminf(c3, (float)(L)); }
#define MP_STEP()    { c0 = floorf(c0 * 0.5f); c1 = floorf(c1 * 0.5f); \
                       c2 = floorf(c2 * 0.5f); c3 = floorf(c3 * 0.5f); }
            CONV_STEP(293); CONV_STEP(291); MP_STEP();
            CONV_STEP(143); CONV_STEP(141); MP_STEP();
            CONV_STEP(68);  CONV_STEP(66);  CONV_STEP(64); MP_STEP();
            CONV_STEP(29);  CONV_STEP(27);  CONV_STEP(25); MP_STEP();
            CONV_STEP(10);  CONV_STEP(8);   CONV_STEP(6);
#undef CONV_STEP
#undef MP_STEP
            int xi = (int)c0, yi = (int)c1, xf = (int)c2, yf = (int)c3;
            int wx = xf + 1 - xi, wy = yf + 1 - yi;
            int kid;
            if (!on || wx <= 0 || wy <= 0 || xi > 6 || yi > 6 || xf < 0 || yf < 0) kid = 2401;
            else kid = ((xi * 7 + yi) * 7 + xf) * 7 + yf;
            int e = b * NKEY + kid;
            s_key[idx] = e;
            s_used[e] = 1;
        }
        __syncthreads();
        // scan: 19 slots per thread (256*19 = 4864 >= 4804)
        int base = tid * 19;
        uint32_t mask = 0;
        int cnt = 0;
#pragma unroll
        for (int u = 0; u < 19; u++) {
            int e = base + u;
            int v = (e < TOTKEY) ? s_used[e] : 0;
            mask |= (uint32_t)v << u;
            cnt += v;
        }
        int x = cnt;
        for (int d = 1; d < 32; d <<= 1) {
            int y = __shfl_up_sync(0xffffffffu, x, d);
            if (lane >= d) x += y;
        }
        if (lane == 31) wsum[wid] = x;
        __syncthreads();
        if (tid == 0) {
            int acc = 0;
#pragma unroll
            for (int wv = 0; wv < 8; wv++) { int t2 = wsum[wv]; wsum[wv] = acc; acc += t2; }
        }
        __syncthreads();
        int off = wsum[wid] + (x - cnt);
#pragma unroll
        for (int u = 0; u < 19; u++) {
            int e = base + u;
            if (e < TOTKEY) {
                if ((mask >> u) & 1u) {
                    s_used[e] = off;
                    g_keyOfRow[off] = e;
                    off++;
                } else {
                    s_used[e] = -1;
                }
            }
        }
        if (tid == NTHR - 1) g_M[0] = off;
        __syncthreads();
        for (int idx = tid; idx < NTOT; idx += NTHR)
            g_roiRow[idx] = s_used[s_key[idx]];
    }
    grid_barrier(0);

    const int M = g_M[0];

    // ================= phase B: pool (smem-staged, fully coalesced) =================
    {
        float* F_s = sp;            // [49][64]  = 3136 floats
        float* out_s = sp + 3200;   // [64*49]   = 3136 floats
        for (int r = bid; r < M; r += NBLK) {
            int e = g_keyOfRow[r];
            int b = e / NKEY;
            int kid = e % NKEY;
            float* Arow = g_A + (size_t)r * DD;
            if (kid == 2401) {
                for (int k = tid; k < DD; k += NTHR) Arow[k] = 0.f;
                continue;
            }
            int yf = kid % 7;
            int xf = (kid / 7) % 7;
            int yi = (kid / 49) % 7;
            int xi = kid / 343;
            int wx = xf + 1 - xi, wy = yf + 1 - yi;
            int bx[8], by[8];
#pragma unroll
            for (int ii = 0; ii < 8; ii++) {
                bx[ii] = xi + (ii * wx) / 7;
                by[ii] = yi + (ii * wy) / 7;
            }
            const int c_loc = tid & 63;
            const int grp = tid >> 6;               // 0..3
            const int ij0 = grp * 13;
            const int ij1 = (grp == 3) ? 49 : ij0 + 13;
            const float* FTb = g_FT + (size_t)b * 49 * CC;
            for (int chunk = 0; chunk < 8; chunk++) {
                const int c0 = chunk * 64;
                __syncthreads();
                // load F_s[p][cl] = g_FT[b][p][c0+cl]  (coalesced: 64 consecutive floats/row)
                for (int idx = tid; idx < 49 * 64; idx += NTHR)
                    F_s[idx] = FTb[(idx >> 6) * CC + c0 + (idx & 63)];
                __syncthreads();
                // compute rect-maxes for my channel + my bins
                for (int ij = ij0; ij < ij1; ij++) {
                    int i = ij / 7, j = ij % 7;
                    int x0 = bx[i], x1 = bx[i + 1];
                    int y0 = by[j], y1 = by[j + 1];
                    float m = -3.0e38f;
                    for (int xx = x0; xx < x1; xx++)
                        for (int yy = y0; yy < y1; yy++)
                            m = fmaxf(m, F_s[(xx * 7 + yy) * 64 + c_loc]);
                    out_s[c_loc * 49 + ij] = (x1 > x0 && y1 > y0) ? m : 0.f;
                }
                __syncthreads();
                // contiguous copy: g_A[r][c0*49 .. c0*49+3136) (coalesced)
                float* dst = Arow + c0 * 49;
                for (int idx = tid; idx < 64 * 49; idx += NTHR)
                    dst[idx] = out_s[idx];
            }
        }
    }
    grid_barrier(1);

    // ================= phase C: split-K tf32 GEMM (98 x mtiles work units) =========
    {
        float* sA = sp;           // 2304 floats
        float* sW = sp + GM_BM * SASTR;
        const int mtiles = (M + GM_BM - 1) / GM_BM;
        const int warpM = wid & 1;
        const int warpN = wid >> 1;
        const int nfBase = (warpN == 0) ? 0 : 1 + warpN * 6;
        const int nfCnt = (warpN == 0) ? 7 : 6;
        const int arr0 = tid >> 3, akq = tid & 7;
        const int arr1 = (tid + 256) >> 3;
        int wn[7];
        const int wkq = tid & 7;
#pragma unroll
        for (int u = 0; u < 6; u++) wn[u] = (tid + u * 256) >> 3;
        const bool w6v = tid < 64;
        wn[6] = (tid + 1536) >> 3;

        for (int pair = bid; pair < KSPLIT * mtiles; pair += NBLK) {
            const int ksb = pair % KSPLIT;
            const int mBase = (pair / KSPLIT) * GM_BM;
            const int k0 = ksb * KCHUNK;
            float4 pa0, pa1, pw[7];

            auto fetch = [&](int slab) {
                int g0 = mBase + arr0, g1 = mBase + arr1;
                pa0 = make_float4(0.f, 0.f, 0.f, 0.f);
                pa1 = make_float4(0.f, 0.f, 0.f, 0.f);
                const size_t kb = k0 + slab * 32 + akq * 4;
                if (g0 < M) pa0 = *reinterpret_cast<const float4*>(&g_A[(size_t)g0 * DD + kb]);
                if (g1 < M) pa1 = *reinterpret_cast<const float4*>(&g_A[(size_t)g1 * DD + kb]);
                const size_t kw = k0 + slab * 32 + wkq * 4;
#pragma unroll
                for (int u = 0; u < 6; u++)
                    pw[u] = *reinterpret_cast<const float4*>(&w1[(size_t)wn[u] * DD + kw]);
                if (w6v) pw[6] = *reinterpret_cast<const float4*>(&w1[(size_t)wn[6] * DD + kw]);
            };
            auto commit = [&]() {
                *reinterpret_cast<float4*>(&sA[arr0 * SASTR + akq * 4]) = pa0;
                *reinterpret_cast<float4*>(&sA[arr1 * SASTR + akq * 4]) = pa1;
#pragma unroll
                for (int u = 0; u < 6; u++)
                    *reinterpret_cast<float4*>(&sW[wn[u] * SASTR + wkq * 4]) = pw[u];
                if (w6v) *reinterpret_cast<float4*>(&sW[wn[6] * SASTR + wkq * 4]) = pw[6];
            };

            float acc[2][7][4];
#pragma unroll
            for (int f = 0; f < 2; f++)
#pragma unroll
                for (int i = 0; i < 7; i++)
#pragma unroll
                    for (int j = 0; j < 4; j++) acc[f][i][j] = 0.f;

            fetch(0);
            __syncthreads();   // prior iteration / phase done with sp
            commit();
            __syncthreads();

            for (int slab = 0; slab < NSLAB; slab++) {
                if (slab + 1 < NSLAB) fetch(slab + 1);
#pragma unroll
                for (int ks = 0; ks < 4; ks++) {
                    int kcol = ks * 8 + (lane & 3);
                    int row0 = warpM * 32 + (lane >> 2);
                    uint32_t a00 = __float_as_uint(sA[row0 * SASTR + kcol]);
                    uint32_t a01 = __float_as_uint(sA[(row0 + 8) * SASTR + kcol]);
                    uint32_t a02 = __float_as_uint(sA[row0 * SASTR + kcol + 4]);
                    uint32_t a03 = __float_as_uint(sA[(row0 + 8) * SASTR + kcol + 4]);
                    uint32_t a10 = __float_as_uint(sA[(row0 + 16) * SASTR + kcol]);
                    uint32_t a11 = __float_as_uint(sA[(row0 + 24) * SASTR + kcol]);
                    uint32_t a12 = __float_as_uint(sA[(row0 + 16) * SASTR + kcol + 4]);
                    uint32_t a13 = __float_as_uint(sA[(row0 + 24) * SASTR + kcol + 4]);
#pragma unroll
                    for (int nf = 0; nf < 7; nf++) {
                        if (nf < nfCnt) {
                            int n0 = (nfBase + nf) * 8 + (lane >> 2);
                            uint32_t b0 = __float_as_uint(sW[n0 * SASTR + kcol]);
                            uint32_t b1 = __float_as_uint(sW[n0 * SASTR + kcol + 4]);
                            mma_tf32(acc[0][nf][0], acc[0][nf][1], acc[0][nf][2], acc[0][nf][3],
                                     a00, a01, a02, a03, b0, b1);
                            mma_tf32(acc[1][nf][0], acc[1][nf][1], acc[1][nf][2], acc[1][nf][3],
                                     a10, a11, a12, a13, b0, b1);
                        }
                    }
                }
                if (slab + 1 < NSLAB) {
                    __syncthreads();
                    commit();
                    __syncthreads();
                }
            }
#pragma unroll
            for (int f = 0; f < 2; f++) {
                int rowA = mBase + warpM * 32 + f * 16 + (lane >> 2);
                int rowB = rowA + 8;
#pragma unroll
                for (int nf = 0; nf < 7; nf++) {
                    if (nf < nfCnt) {
                        int col = (nfBase + nf) * 8 + (lane & 3) * 2;
                        if (rowA < MAXROWS)
                            *reinterpret_cast<float2*>(&g_P[((size_t)rowA * KSPLIT + ksb) * H1 + col]) =
                                make_float2(acc[f][nf][0], acc[f][nf][1]);
                        if (rowB < MAXROWS)
                            *reinterpret_cast<float2*>(&g_P[((size_t)rowB * KSPLIT + ksb) * H1 + col]) =
                                make_float2(acc[f][nf][2], acc[f][nf][3]);
                    }
                }
            }
        }
    }
    grid_barrier(2);

    // ================= phase D: reduce + MLP =================
    {
        float* h1s = sp;
        float* h2s = sp + H1;
        for (int r = bid; r < M; r += NBLK) {
            __syncthreads();
            {
                const float* Pr = g_P + (size_t)r * KSPLIT * H1;
                if (tid < H1) {
                    float s = b1[tid];
#pragma unroll 14
                    for (int ks = 0; ks < KSPLIT; ks++)
                        s += Pr[ks * H1 + tid];
                    h1s[tid] = fmaxf(s, 0.f);
                }
            }
            __syncthreads();
            for (int j = wid; j < H2; j += 16) {
                int j2 = j + 8;
                bool v2 = j2 < H2;
                const float* wr0 = w2 + j * H1;
                const float* wr1 = w2 + (v2 ? j2 : j) * H1;
                float s0 = 0.f, s1 = 0.f;
#pragma unroll
                for (int k = lane; k < H1; k += 32) {
                    float hk = h1s[k];
                    s0 += wr0[k] * hk;
                    s1 += wr1[k] * hk;
                }
#pragma unroll
                for (int d = 16; d > 0; d >>= 1) {
                    s0 += __shfl_xor_sync(0xffffffffu, s0, d);
                    s1 += __shfl_xor_sync(0xffffffffu, s1, d);
                }
                if (lane == 0) {
                    h2s[j] = fmaxf(s0 + b2[j], 0.f);
                    if (v2) h2s[j2] = fmaxf(s1 + b2[j2], 0.f);
                }
            }
            __syncthreads();
            for (int q = wid; q < 85; q += 16) {
                int q2 = q + 8;
                bool v2 = q2 < 85;
                const float *wr0, *wr1;
                float bias0, bias1 = 0.f;
                if (q < KC) { wr0 = w3 + q * H2;        bias0 = b3[q]; }
                else        { wr0 = w4 + (q - KC) * H2; bias0 = b4[q - KC]; }
                if (v2) {
                    if (q2 < KC) { wr1 = w3 + q2 * H2;        bias1 = b3[q2]; }
                    else         { wr1 = w4 + (q2 - KC) * H2; bias1 = b4[q2 - KC]; }
                } else wr1 = wr0;
                float s0 = 0.f, s1 = 0.f;
#pragma unroll
                for (int k = lane; k < H2; k += 32) {
                    float hk = h2s[k];
                    s0 += wr0[k] * hk;
                    s1 += wr1[k] * hk;
                }
#pragma unroll
                for (int d = 16; d > 0; d >>= 1) {
                    s0 += __shfl_xor_sync(0xffffffffu, s0, d);
                    s1 += __shfl_xor_sync(0xffffffffu, s1, d);
                }
                if (lane == 0) {
                    g_out85[r * 85 + q] = s0 + bias0;
                    if (v2) g_out85[r * 85 + q2] = s1 + bias1;
                }
            }
        }
    }
    grid_barrier(3);

    // ================= phase E: scatter =================
    for (int idx = bid * NTHR + tid; idx < NTOT * 85; idx += NBLK * NTHR) {
        int bn = idx / 85;
        int q = idx % 85;
        int r = g_roiRow[bn];
        float val = g_out85[r * 85 + q];
        if (q < KC) {
            out[bn * KC + q] = val;                                        // z1
        } else {
            int k = (q - KC) / KC, cls = (q - KC) % KC;
            int b = bn / NROI, n = bn % NROI;
            out[NTOT * KC + (((b * 4 + k) * NROI + n) * KC + cls)] = val;  // z3
        }
    }
}

// ---------------- launch ----------------
extern "C" void kernel_launch(void* const* d_in, const int* in_sizes, int n_in,
                              void* d_out, int out_size) {
    const float* cfeats = (const float*)d_in[0];
    const float* regcls = (const float*)d_in[1];
    const float* wan    = (const float*)d_in[2];
    const float* han    = (const float*)d_in[3];
    const float* xan    = (const float*)d_in[4];
    const float* yan    = (const float*)d_in[5];
    const float* w1     = (const float*)d_in[6];
    const float* b1     = (const float*)d_in[7];
    const float* w2     = (const float*)d_in[8];
    const float* b2     = (const float*)d_in[9];
    const float* w3     = (const float*)d_in[10];
    const float* b3     = (const float*)d_in[11];
    const float* w4     = (const float*)d_in[12];
    const float* b4     = (const float*)d_in[13];
    float* out = (float*)d_out;

    mega_kernel<<<NBLK, NTHR>>>(cfeats, regcls, wan, han, xan, yan,
                                w1, b1, w2, b2, w3, b3, w4, b4, out);
}

// round 12
// speedup vs baseline: 1.6620x; 1.6620x over previous
#include <cuda_runtime.h>
#include <cuda_bf16.h>
#include <math.h>
#include <stdint.h>

#define BB 2
#define NROI 625
#define NTOT 1250
#define CC 512
#define DD 25088            // 512*49
#define H1 200
#define H2 100
#define KC 17
#define NKEY 2402
#define TOTKEY 4804
#define MAXROWS 1250
#define KSPLIT 98
#define KCHUNK 256
#define NSLAB 8             // KCHUNK/32
#define NBLK 296
#define NTHR 256
#define GM_BM 64
#define SASTR 36

// ---------------- scratch ----------------
__device__ float g_A[(size_t)MAXROWS * DD];
__device__ float g_P[(size_t)MAXROWS * KSPLIT * H1];   // [row][ks][H1]
__device__ float g_FT[BB * 49 * CC];                   // transposed tf32 feats [b][p][c]
__device__ float g_out85[MAXROWS * 85];
__device__ int   g_keyOfRow[TOTKEY];
__device__ int   g_roiRow[NTOT];
__device__ int   g_M[1];
__device__ unsigned long long g_barcnt[8];   // monotonic epochs; never reset

// ---------------- helpers ----------------
__device__ __forceinline__ float tf32r(float x) {
    uint32_t u;
    asm("cvt.rna.tf32.f32 %0, %1;" : "=r"(u) : "f"(x));
    return __uint_as_float(u);
}
__device__ __forceinline__ void mma_tf32(float& d0, float& d1, float& d2, float& d3,
                                         uint32_t a0, uint32_t a1, uint32_t a2, uint32_t a3,
                                         uint32_t b0, uint32_t b1) {
    asm volatile(
        "mma.sync.aligned.m16n8k8.row.col.f32.tf32.tf32.f32 "
        "{%0,%1,%2,%3}, {%4,%5,%6,%7}, {%8,%9}, {%0,%1,%2,%3};\n"
        : "+f"(d0), "+f"(d1), "+f"(d2), "+f"(d3)
        : "r"(a0), "r"(a1), "r"(a2), "r"(a3), "r"(b0), "r"(b1));
}

// monotonic grid barrier: arrivals via atomicAdd; waiting via plain volatile loads.
__device__ __forceinline__ void grid_barrier(int k) {
    __syncthreads();
    if (threadIdx.x == 0) {
        __threadfence();
        unsigned long long my = atomicAdd(&g_barcnt[k], 1ULL) + 1ULL;
        unsigned long long target = ((my - 1ULL) / NBLK + 1ULL) * NBLK;
        volatile unsigned long long* p = (volatile unsigned long long*)&g_barcnt[k];
        while (*p < target) { __nanosleep(60); }
        __threadfence();
    }
    __syncthreads();
}

// ---------------- the megakernel ----------------
__global__ void __launch_bounds__(NTHR, 2) mega_kernel(
    const float* __restrict__ cf, const float* __restrict__ regcls,
    const float* __restrict__ wan, const float* __restrict__ han,
    const float* __restrict__ xan, const float* __restrict__ yan,
    const float* __restrict__ w1, const float* __restrict__ b1,
    const float* __restrict__ w2, const float* __restrict__ b2,
    const float* __restrict__ w3, const float* __restrict__ b3,
    const float* __restrict__ w4, const float* __restrict__ b4,
    float* __restrict__ out)
{
    __shared__ __align__(16) float sp[GM_BM * SASTR + H1 * SASTR];  // 9504 floats = 38KB
    const int tid = threadIdx.x;
    const int bid = blockIdx.x;
    const int lane = tid & 31, wid = tid >> 5;

    // ================= phase A: g_FT build (spread) + decode/dedup (block 0) =======
    {
        const int NF = BB * CC * 49;   // 50176
        for (int i = bid * NTHR + tid; i < NF; i += NBLK * NTHR) {
            float v = tf32r(cf[i]);    // coalesced read
            int p = i % 49;
            int bc = i / 49;
            int c = bc & 511;
            int b = bc >> 9;
            g_FT[(b * 49 + p) * CC + c] = v;
        }
    }
    if (bid == 0) {
        int* s_used = reinterpret_cast<int*>(sp);
        int* s_key = s_used + TOTKEY;
        int* wsum = s_key + NTOT;   // 8 ints
        for (int i = tid; i < TOTKEY; i += NTHR) s_used[i] = 0;
        __syncthreads();
        for (int idx = tid; idx < NTOT; idx += NTHR) {
            int b = idx / NROI;
            int n = idx % NROI;
            const float* reg = regcls + (size_t)b * 5 * NROI;
            float r0 = reg[n];
            float r1 = reg[NROI + n];
            float r2 = reg[2 * NROI + n];
            float r3 = reg[3 * NROI + n];
            float w = wan[n], h = han[n], xa = xan[n], ya = yan[n];
            float wreg = expf(r2) * w;
            float hreg = expf(r3) * h;
            float xreg = r0 * w + xa;
            float yreg = r1 * h + ya;
            float xis = xreg - wreg * 0.5f;
            float yis = yreg - hreg * 0.5f;
            float xfs = xreg + wreg * 0.5f;
            float yfs = yreg + hreg * 0.5f;
            float c0 = floorf(fmaxf(xis, 0.f));
            float c1 = floorf(fmaxf(yis, 0.f));
            float c2 = fminf(ceilf(xfs), 295.f);
            float c3 = fmaxf(ceilf(yfs), 295.f);   // (sic) max, as in source
            bool on = (xis < 296.f) && (yis < 296.f) && (xfs >= 0.f) && (yfs >= 0.f);
#define CONV_STEP(L) { c0 = fmaxf(c0 - 1.f, 0.f); c1 = fmaxf(c1 - 1.f, 0.f); \
                       c2 = fminf(c2, (float)(L)); c3 = fminf(c3, (float)(L)); }
#define MP_STEP()    { c0 = floorf(c0 * 0.5f); c1 = floorf(c1 * 0.5f); \
                       c2 = floorf(c2 * 0.5f); c3 = floorf(c3 * 0.5f); }
            CONV_STEP(293); CONV_STEP(291); MP_STEP();
            CONV_STEP(143); CONV_STEP(141); MP_STEP();
            CONV_STEP(68);  CONV_STEP(66);  CONV_STEP(64); MP_STEP();
            CONV_STEP(29);  CONV_STEP(27);  CONV_STEP(25); MP_STEP();
            CONV_STEP(10);  CONV_STEP(8);   CONV_STEP(6);
#undef CONV_STEP
#undef MP_STEP
            int xi = (int)c0, yi = (int)c1, xf = (int)c2, yf = (int)c3;
            int wx = xf + 1 - xi, wy = yf + 1 - yi;
            int kid;
            if (!on || wx <= 0 || wy <= 0 || xi > 6 || yi > 6 || xf < 0 || yf < 0) kid = 2401;
            else kid = ((xi * 7 + yi) * 7 + xf) * 7 + yf;
            int e = b * NKEY + kid;
            s_key[idx] = e;
            s_used[e] = 1;
        }
        __syncthreads();
        // scan: 19 slots per thread (256*19 = 4864 >= 4804)
        int base = tid * 19;
        uint32_t mask = 0;
        int cnt = 0;
#pragma unroll
        for (int u = 0; u < 19; u++) {
            int e = base + u;
            int v = (e < TOTKEY) ? s_used[e] : 0;
            mask |= (uint32_t)v << u;
            cnt += v;
        }
        int x = cnt;
        for (int d = 1; d < 32; d <<= 1) {
            int y = __shfl_up_sync(0xffffffffu, x, d);
            if (lane >= d) x += y;
        }
        if (lane == 31) wsum[wid] = x;
        __syncthreads();
        if (tid == 0) {
            int acc = 0;
#pragma unroll
            for (int wv = 0; wv < 8; wv++) { int t2 = wsum[wv]; wsum[wv] = acc; acc += t2; }
        }
        __syncthreads();
        int off = wsum[wid] + (x - cnt);
#pragma unroll
        for (int u = 0; u < 19; u++) {
            int e = base + u;
            if (e < TOTKEY) {
                if ((mask >> u) & 1u) {
                    s_used[e] = off;
                    g_keyOfRow[off] = e;
                    off++;
                } else {
                    s_used[e] = -1;
                }
            }
        }
        if (tid == NTHR - 1) g_M[0] = off;
        __syncthreads();
        for (int idx = tid; idx < NTOT; idx += NTHR)
            g_roiRow[idx] = s_used[s_key[idx]];
    }
    grid_barrier(0);

    const int M = g_M[0];

    // ====== phase B: pool — coalesced g_FT reads -> register compute -> smem-transposed coalesced writes
    {
        float* out_s = sp;          // [128][49] = 6272 floats (25 KB)
        const int c_loc = tid & 127;
        const int half = tid >> 7;          // 0: bins 0..24, 1: bins 25..48
        const int ij0 = half * 25;
        const int ij1 = half ? 49 : 25;
        for (int r = bid; r < M; r += NBLK) {
            int e = g_keyOfRow[r];
            int b = e / NKEY;
            int kid = e % NKEY;
            float* Arow = g_A + (size_t)r * DD;
            if (kid == 2401) {
                for (int k = tid; k < DD; k += NTHR) Arow[k] = 0.f;
                continue;
            }
            int yf = kid % 7;
            int xf = (kid / 7) % 7;
            int yi = (kid / 49) % 7;
            int xi = kid / 343;
            int wx = xf + 1 - xi, wy = yf + 1 - yi;
            int bx[8], by[8];
#pragma unroll
            for (int ii = 0; ii < 8; ii++) {
                bx[ii] = xi + (ii * wx) / 7;
                by[ii] = yi + (ii * wy) / 7;
            }
            const float* FTb = g_FT + (size_t)b * 49 * CC;
            for (int chunk = 0; chunk < 4; chunk++) {
                const int c = chunk * 128 + c_loc;
                float v[49];
#pragma unroll
                for (int p = 0; p < 49; p++) v[p] = FTb[p * CC + c];  // coalesced
                for (int ij = ij0; ij < ij1; ij++) {
                    int i = ij / 7, j = ij % 7;
                    int x0 = bx[i], x1 = bx[i + 1];
                    int y0 = by[j], y1 = by[j + 1];
                    float m = -3.0e38f;
                    for (int xx = x0; xx < x1; xx++)
                        for (int yy = y0; yy < y1; yy++)
                            m = fmaxf(m, v[xx * 7 + yy]);
                    out_s[c_loc * 49 + ij] = (x1 > x0 && y1 > y0) ? m : 0.f;
                }
                __syncthreads();
                float* dst = Arow + chunk * 128 * 49;
                for (int idx = tid; idx < 128 * 49; idx += NTHR)   // contiguous, coalesced
                    dst[idx] = out_s[idx];
                __syncthreads();
            }
        }
    }
    grid_barrier(1);

    // ================= phase C: split-K tf32 GEMM (98 x mtiles work units) =========
    {
        float* sA = sp;           // 2304 floats
        float* sW = sp + GM_BM * SASTR;
        const int mtiles = (M + GM_BM - 1) / GM_BM;
        const int warpM = wid & 1;
        const int warpN = wid >> 1;
        const int nfBase = (warpN == 0) ? 0 : 1 + warpN * 6;
        const int nfCnt = (warpN == 0) ? 7 : 6;
        const int arr0 = tid >> 3, akq = tid & 7;
        const int arr1 = (tid + 256) >> 3;
        int wn[7];
        const int wkq = tid & 7;
#pragma unroll
        for (int u = 0; u < 6; u++) wn[u] = (tid + u * 256) >> 3;
        const bool w6v = tid < 64;
        wn[6] = (tid + 1536) >> 3;

        for (int pair = bid; pair < KSPLIT * mtiles; pair += NBLK) {
            const int ksb = pair % KSPLIT;
            const int mBase = (pair / KSPLIT) * GM_BM;
            const int k0 = ksb * KCHUNK;
            float4 pa0, pa1, pw[7];

            auto fetch = [&](int slab) {
                int g0 = mBase + arr0, g1 = mBase + arr1;
                pa0 = make_float4(0.f, 0.f, 0.f, 0.f);
                pa1 = make_float4(0.f, 0.f, 0.f, 0.f);
                const size_t kb = k0 + slab * 32 + akq * 4;
                if (g0 < M) pa0 = *reinterpret_cast<const float4*>(&g_A[(size_t)g0 * DD + kb]);
                if (g1 < M) pa1 = *reinterpret_cast<const float4*>(&g_A[(size_t)g1 * DD + kb]);
                const size_t kw = k0 + slab * 32 + wkq * 4;
#pragma unroll
                for (int u = 0; u < 6; u++)
                    pw[u] = *reinterpret_cast<const float4*>(&w1[(size_t)wn[u] * DD + kw]);
                if (w6v) pw[6] = *reinterpret_cast<const float4*>(&w1[(size_t)wn[6] * DD + kw]);
            };
            auto commit = [&]() {
                *reinterpret_cast<float4*>(&sA[arr0 * SASTR + akq * 4]) = pa0;
                *reinterpret_cast<float4*>(&sA[arr1 * SASTR + akq * 4]) = pa1;
#pragma unroll
                for (int u = 0; u < 6; u++)
                    *reinterpret_cast<float4*>(&sW[wn[u] * SASTR + wkq * 4]) = pw[u];
                if (w6v) *reinterpret_cast<float4*>(&sW[wn[6] * SASTR + wkq * 4]) = pw[6];
            };

            float acc[2][7][4];
#pragma unroll
            for (int f = 0; f < 2; f++)
#pragma unroll
                for (int i = 0; i < 7; i++)
#pragma unroll
                    for (int j = 0; j < 4; j++) acc[f][i][j] = 0.f;

            fetch(0);
            __syncthreads();   // prior iteration / phase done with sp
            commit();
            __syncthreads();

            for (int slab = 0; slab < NSLAB; slab++) {
                if (slab + 1 < NSLAB) fetch(slab + 1);
#pragma unroll
                for (int ks = 0; ks < 4; ks++) {
                    int kcol = ks * 8 + (lane & 3);
                    int row0 = warpM * 32 + (lane >> 2);
                    uint32_t a00 = __float_as_uint(sA[row0 * SASTR + kcol]);
                    uint32_t a01 = __float_as_uint(sA[(row0 + 8) * SASTR + kcol]);
                    uint32_t a02 = __float_as_uint(sA[row0 * SASTR + kcol + 4]);
                    uint32_t a03 = __float_as_uint(sA[(row0 + 8) * SASTR + kcol + 4]);
                    uint32_t a10 = __float_as_uint(sA[(row0 + 16) * SASTR + kcol]);
                    uint32_t a11 = __float_as_uint(sA[(row0 + 24) * SASTR + kcol]);
                    uint32_t a12 = __float_as_uint(sA[(row0 + 16) * SASTR + kcol + 4]);
                    uint32_t a13 = __float_as_uint(sA[(row0 + 24) * SASTR + kcol + 4]);
#pragma unroll
                    for (int nf = 0; nf < 7; nf++) {
                        if (nf < nfCnt) {
                            int n0 = (nfBase + nf) * 8 + (lane >> 2);
                            uint32_t b0 = __float_as_uint(sW[n0 * SASTR + kcol]);
                            uint32_t b1 = __float_as_uint(sW[n0 * SASTR + kcol + 4]);
                            mma_tf32(acc[0][nf][0], acc[0][nf][1], acc[0][nf][2], acc[0][nf][3],
                                     a00, a01, a02, a03, b0, b1);
                            mma_tf32(acc[1][nf][0], acc[1][nf][1], acc[1][nf][2], acc[1][nf][3],
                                     a10, a11, a12, a13, b0, b1);
                        }
                    }
                }
                if (slab + 1 < NSLAB) {
                    __syncthreads();
                    commit();
                    __syncthreads();
                }
            }
#pragma unroll
            for (int f = 0; f < 2; f++) {
                int rowA = mBase + warpM * 32 + f * 16 + (lane >> 2);
                int rowB = rowA + 8;
#pragma unroll
                for (int nf = 0; nf < 7; nf++) {
                    if (nf < nfCnt) {
                        int col = (nfBase + nf) * 8 + (lane & 3) * 2;
                        if (rowA < MAXROWS)
                            *reinterpret_cast<float2*>(&g_P[((size_t)rowA * KSPLIT + ksb) * H1 + col]) =
                                make_float2(acc[f][nf][0], acc[f][nf][1]);
                        if (rowB < MAXROWS)
                            *reinterpret_cast<float2*>(&g_P[((size_t)rowB * KSPLIT + ksb) * H1 + col]) =
                                make_float2(acc[f][nf][2], acc[f][nf][3]);
                    }
                }
            }
        }
    }
    grid_barrier(2);

    // ================= phase D: reduce + MLP =================
    {
        float* h1s = sp;
        float* h2s = sp + H1;
        for (int r = bid; r < M; r += NBLK) {
            __syncthreads();
            {
                const float* Pr = g_P + (size_t)r * KSPLIT * H1;
                if (tid < H1) {
                    float s = b1[tid];
#pragma unroll 14
                    for (int ks = 0; ks < KSPLIT; ks++)
                        s += Pr[ks * H1 + tid];
                    h1s[tid] = fmaxf(s, 0.f);
                }
            }
            __syncthreads();
            for (int j = wid; j < H2; j += 16) {
                int j2 = j + 8;
                bool v2 = j2 < H2;
                const float* wr0 = w2 + j * H1;
                const float* wr1 = w2 + (v2 ? j2 : j) * H1;
                float s0 = 0.f, s1 = 0.f;
#pragma unroll
                for (int k = lane; k < H1; k += 32) {
                    float hk = h1s[k];
                    s0 += wr0[k] * hk;
                    s1 += wr1[k] * hk;
                }
#pragma unroll
                for (int d = 16; d > 0; d >>= 1) {
                    s0 += __shfl_xor_sync(0xffffffffu, s0, d);
                    s1 += __shfl_xor_sync(0xffffffffu, s1, d);
                }
                if (lane == 0) {
                    h2s[j] = fmaxf(s0 + b2[j], 0.f);
                    if (v2) h2s[j2] = fmaxf(s1 + b2[j2], 0.f);
                }
            }
            __syncthreads();
            for (int q = wid; q < 85; q += 16) {
                int q2 = q + 8;
                bool v2 = q2 < 85;
                const float *wr0, *wr1;
                float bias0, bias1 = 0.f;
                if (q < KC) { wr0 = w3 + q * H2;        bias0 = b3[q]; }
                else        { wr0 = w4 + (q - KC) * H2; bias0 = b4[q - KC]; }
                if (v2) {
                    if (q2 < KC) { wr1 = w3 + q2 * H2;        bias1 = b3[q2]; }
                    else         { wr1 = w4 + (q2 - KC) * H2; bias1 = b4[q2 - KC]; }
                } else wr1 = wr0;
                float s0 = 0.f, s1 = 0.f;
#pragma unroll
                for (int k = lane; k < H2; k += 32) {
                    float hk = h2s[k];
                    s0 += wr0[k] * hk;
                    s1 += wr1[k] * hk;
                }
#pragma unroll
                for (int d = 16; d > 0; d >>= 1) {
                    s0 += __shfl_xor_sync(0xffffffffu, s0, d);
                    s1 += __shfl_xor_sync(0xffffffffu, s1, d);
                }
                if (lane == 0) {
                    g_out85[r * 85 + q] = s0 + bias0;
                    if (v2) g_out85[r * 85 + q2] = s1 + bias1;
                }
            }
        }
    }
    grid_barrier(3);

    // ================= phase E: scatter =================
    for (int idx = bid * NTHR + tid; idx < NTOT * 85; idx += NBLK * NTHR) {
        int bn = idx / 85;
        int q = idx % 85;
        int r = g_roiRow[bn];
        float val = g_out85[r * 85 + q];
        if (q < KC) {
            out[bn * KC + q] = val;                                        // z1
        } else {
            int k = (q - KC) / KC, cls = (q - KC) % KC;
            int b = bn / NROI, n = bn % NROI;
            out[NTOT * KC + (((b * 4 + k) * NROI + n) * KC + cls)] = val;  // z3
        }
    }
}

// ---------------- launch ----------------
extern "C" void kernel_launch(void* const* d_in, const int* in_sizes, int n_in,
                              void* d_out, int out_size) {
    const float* cfeats = (const float*)d_in[0];
    const float* regcls = (const float*)d_in[1];
    const float* wan    = (const float*)d_in[2];
    const float* han    = (const float*)d_in[3];
    const float* xan    = (const float*)d_in[4];
    const float* yan    = (const float*)d_in[5];
    const float* w1     = (const float*)d_in[6];
    const float* b1     = (const float*)d_in[7];
    const float* w2     = (const float*)d_in[8];
    const float* b2     = (const float*)d_in[9];
    const float* w3     = (const float*)d_in[10];
    const float* b3     = (const float*)d_in[11];
    const float* w4     = (const float*)d_in[12];
    const float* b4     = (const float*)d_in[13];
    float* out = (float*)d_out;

    mega_kernel<<<NBLK, NTHR>>>(cfeats, regcls, wan, han, xan, yan,
                                w1, b1, w2, b2, w3, b3, w4, b4, out);
}

// round 13
// speedup vs baseline: 1.6764x; 1.0087x over previous
#include <cuda_runtime.h>
#include <cuda_bf16.h>
#include <math.h>
#include <stdint.h>

#define BB 2
#define NROI 625
#define NTOT 1250
#define CC 512
#define DD 25088            // 512*49
#define H1 200
#define H2 100
#define KC 17
#define NKEY 2402
#define TOTKEY 4804
#define MAXROWS 1250
#define KSPLIT 98
#define KCHUNK 256
#define NSLAB 8             // KCHUNK/32
#define NBLK 296
#define NTHR 256
#define GM_BM 64
#define SASTR 36

// ---------------- scratch ----------------
__device__ float g_A[(size_t)MAXROWS * DD];
__device__ float g_P[(size_t)MAXROWS * KSPLIT * H1];   // [row][ks][H1]
__device__ float g_FT[BB * 49 * CC];                   // transposed tf32 feats [b][p][c]
__device__ float g_out85[MAXROWS * 85];
__device__ int   g_keyOfRow[TOTKEY];
__device__ int   g_roiRow[NTOT];
__device__ int   g_M[1];
__device__ unsigned long long g_barcnt[8];   // monotonic epochs; never reset

// ---------------- helpers ----------------
__device__ __forceinline__ float tf32r(float x) {
    uint32_t u;
    asm("cvt.rna.tf32.f32 %0, %1;" : "=r"(u) : "f"(x));
    return __uint_as_float(u);
}
__device__ __forceinline__ void mma_tf32(float& d0, float& d1, float& d2, float& d3,
                                         uint32_t a0, uint32_t a1, uint32_t a2, uint32_t a3,
                                         uint32_t b0, uint32_t b1) {
    asm volatile(
        "mma.sync.aligned.m16n8k8.row.col.f32.tf32.tf32.f32 "
        "{%0,%1,%2,%3}, {%4,%5,%6,%7}, {%8,%9}, {%0,%1,%2,%3};\n"
        : "+f"(d0), "+f"(d1), "+f"(d2), "+f"(d3)
        : "r"(a0), "r"(a1), "r"(a2), "r"(a3), "r"(b0), "r"(b1));
}

// monotonic grid barrier: arrivals via atomicAdd; waiting via plain volatile loads.
__device__ __forceinline__ void grid_barrier(int k) {
    __syncthreads();
    if (threadIdx.x == 0) {
        __threadfence();
        unsigned long long my = atomicAdd(&g_barcnt[k], 1ULL) + 1ULL;
        unsigned long long target = ((my - 1ULL) / NBLK + 1ULL) * NBLK;
        volatile unsigned long long* p = (volatile unsigned long long*)&g_barcnt[k];
        while (*p < target) { __nanosleep(60); }
        __threadfence();
    }
    __syncthreads();
}

// ---------------- the megakernel ----------------
__global__ void __launch_bounds__(NTHR, 2) mega_kernel(
    const float* __restrict__ cf, const float* __restrict__ regcls,
    const float* __restrict__ wan, const float* __restrict__ han,
    const float* __restrict__ xan, const float* __restrict__ yan,
    const float* __restrict__ w1, const float* __restrict__ b1,
    const float* __restrict__ w2, const float* __restrict__ b2,
    const float* __restrict__ w3, const float* __restrict__ b3,
    const float* __restrict__ w4, const float* __restrict__ b4,
    float* __restrict__ out)
{
    __shared__ __align__(16) float sp[GM_BM * SASTR + H1 * SASTR];  // 9504 floats = 38KB
    const int tid = threadIdx.x;
    const int bid = blockIdx.x;
    const int lane = tid & 31, wid = tid >> 5;

    // ================= phase A: g_FT build + w1 L2 prefetch + decode/dedup (block 0)
    {
        const int NF = BB * CC * 49;   // 50176
        for (int i = bid * NTHR + tid; i < NF; i += NBLK * NTHR) {
            float v = tf32r(cf[i]);    // coalesced read
            int p = i % 49;
            int bc = i / 49;
            int c = bc & 511;
            int b = bc >> 9;
            g_FT[(b * 49 + p) * CC + c] = v;
        }
    }
    if (bid != 0) {
        // warm L2 with all of w1 (20 MB) while block 0 runs the control path.
        const size_t NLINES = ((size_t)H1 * DD * 4) / 128;   // 156,800 lines
        const char* base = (const char*)w1;
        for (size_t i = (size_t)(bid - 1) * NTHR + tid; i < NLINES;
             i += (size_t)(NBLK - 1) * NTHR) {
            asm volatile("prefetch.global.L2 [%0];" :: "l"(base + i * 128));
        }
    } else {
        int* s_used = reinterpret_cast<int*>(sp);
        int* s_key = s_used + TOTKEY;
        int* wsum = s_key + NTOT;   // 8 ints
        for (int i = tid; i < TOTKEY; i += NTHR) s_used[i] = 0;
        __syncthreads();
        for (int idx = tid; idx < NTOT; idx += NTHR) {
            int b = idx / NROI;
            int n = idx % NROI;
            const float* reg = regcls + (size_t)b * 5 * NROI;
            float r0 = reg[n];
            float r1 = reg[NROI + n];
            float r2 = reg[2 * NROI + n];
            float r3 = reg[3 * NROI + n];
            float w = wan[n], h = han[n], xa = xan[n], ya = yan[n];
            float wreg = expf(r2) * w;
            float hreg = expf(r3) * h;
            float xreg = r0 * w + xa;
            float yreg = r1 * h + ya;
            float xis = xreg - wreg * 0.5f;
            float yis = yreg - hreg * 0.5f;
            float xfs = xreg + wreg * 0.5f;
            float yfs = yreg + hreg * 0.5f;
            float c0 = floorf(fmaxf(xis, 0.f));
            float c1 = floorf(fmaxf(yis, 0.f));
            float c2 = fminf(ceilf(xfs), 295.f);
            float c3 = fmaxf(ceilf(yfs), 295.f);   // (sic) max, as in source
            bool on = (xis < 296.f) && (yis < 296.f) && (xfs >= 0.f) && (yfs >= 0.f);
#define CONV_STEP(L) { c0 = fmaxf(c0 - 1.f, 0.f); c1 = fmaxf(c1 - 1.f, 0.f); \
                       c2 = fminf(c2, (float)(L)); c3 = fminf(c3, (float)(L)); }
#define MP_STEP()    { c0 = floorf(c0 * 0.5f); c1 = floorf(c1 * 0.5f); \
                       c2 = floorf(c2 * 0.5f); c3 = floorf(c3 * 0.5f); }
            CONV_STEP(293); CONV_STEP(291); MP_STEP();
            CONV_STEP(143); CONV_STEP(141); MP_STEP();
            CONV_STEP(68);  CONV_STEP(66);  CONV_STEP(64); MP_STEP();
            CONV_STEP(29);  CONV_STEP(27);  CONV_STEP(25); MP_STEP();
            CONV_STEP(10);  CONV_STEP(8);   CONV_STEP(6);
#undef CONV_STEP
#undef MP_STEP
            int xi = (int)c0, yi = (int)c1, xf = (int)c2, yf = (int)c3;
            int wx = xf + 1 - xi, wy = yf + 1 - yi;
            int kid;
            if (!on || wx <= 0 || wy <= 0 || xi > 6 || yi > 6 || xf < 0 || yf < 0) kid = 2401;
            else kid = ((xi * 7 + yi) * 7 + xf) * 7 + yf;
            int e = b * NKEY + kid;
            s_key[idx] = e;
            s_used[e] = 1;
        }
        __syncthreads();
        // scan: 19 slots per thread (256*19 = 4864 >= 4804)
        int base = tid * 19;
        uint32_t mask = 0;
        int cnt = 0;
#pragma unroll
        for (int u = 0; u < 19; u++) {
            int e = base + u;
            int v = (e < TOTKEY) ? s_used[e] : 0;
            mask |= (uint32_t)v << u;
            cnt += v;
        }
        int x = cnt;
        for (int d = 1; d < 32; d <<= 1) {
            int y = __shfl_up_sync(0xffffffffu, x, d);
            if (lane >= d) x += y;
        }
        if (lane == 31) wsum[wid] = x;
        __syncthreads();
        if (tid == 0) {
            int acc = 0;
#pragma unroll
            for (int wv = 0; wv < 8; wv++) { int t2 = wsum[wv]; wsum[wv] = acc; acc += t2; }
        }
        __syncthreads();
        int off = wsum[wid] + (x - cnt);
#pragma unroll
        for (int u = 0; u < 19; u++) {
            int e = base + u;
            if (e < TOTKEY) {
                if ((mask >> u) & 1u) {
                    s_used[e] = off;
                    g_keyOfRow[off] = e;
                    off++;
                } else {
                    s_used[e] = -1;
                }
            }
        }
        if (tid == NTHR - 1) g_M[0] = off;
        __syncthreads();
        for (int idx = tid; idx < NTOT; idx += NTHR)
            g_roiRow[idx] = s_used[s_key[idx]];
    }
    grid_barrier(0);

    const int M = g_M[0];

    // ====== phase B: pool — coalesced g_FT reads -> register compute -> smem-transposed coalesced writes
    {
        float* out_s = sp;          // [128][49] = 6272 floats (25 KB)
        const int c_loc = tid & 127;
        const int half = tid >> 7;          // 0: bins 0..24, 1: bins 25..48
        const int ij0 = half * 25;
        const int ij1 = half ? 49 : 25;
        for (int r = bid; r < M; r += NBLK) {
            int e = g_keyOfRow[r];
            int b = e / NKEY;
            int kid = e % NKEY;
            float* Arow = g_A + (size_t)r * DD;
            if (kid == 2401) {
                for (int k = tid; k < DD; k += NTHR) Arow[k] = 0.f;
                continue;
            }
            int yf = kid % 7;
            int xf = (kid / 7) % 7;
            int yi = (kid / 49) % 7;
            int xi = kid / 343;
            int wx = xf + 1 - xi, wy = yf + 1 - yi;
            int bx[8], by[8];
#pragma unroll
            for (int ii = 0; ii < 8; ii++) {
                bx[ii] = xi + (ii * wx) / 7;
                by[ii] = yi + (ii * wy) / 7;
            }
            const float* FTb = g_FT + (size_t)b * 49 * CC;
            for (int chunk = 0; chunk < 4; chunk++) {
                const int c = chunk * 128 + c_loc;
                float v[49];
#pragma unroll
                for (int p = 0; p < 49; p++) v[p] = FTb[p * CC + c];  // coalesced
                for (int ij = ij0; ij < ij1; ij++) {
                    int i = ij / 7, j = ij % 7;
                    int x0 = bx[i], x1 = bx[i + 1];
                    int y0 = by[j], y1 = by[j + 1];
                    float m = -3.0e38f;
                    for (int xx = x0; xx < x1; xx++)
                        for (int yy = y0; yy < y1; yy++)
                            m = fmaxf(m, v[xx * 7 + yy]);
                    out_s[c_loc * 49 + ij] = (x1 > x0 && y1 > y0) ? m : 0.f;
                }
                __syncthreads();
                float* dst = Arow + chunk * 128 * 49;
                for (int idx = tid; idx < 128 * 49; idx += NTHR)   // contiguous, coalesced
                    dst[idx] = out_s[idx];
                __syncthreads();
            }
        }
    }
    grid_barrier(1);

    // ================= phase C: split-K tf32 GEMM (98 x mtiles work units) =========
    {
        float* sA = sp;           // 2304 floats
        float* sW = sp + GM_BM * SASTR;
        const int mtiles = (M + GM_BM - 1) / GM_BM;
        const int warpM = wid & 1;
        const int warpN = wid >> 1;
        const int nfBase = (warpN == 0) ? 0 : 1 + warpN * 6;
        const int nfCnt = (warpN == 0) ? 7 : 6;
        const int arr0 = tid >> 3, akq = tid & 7;
        const int arr1 = (tid + 256) >> 3;
        int wn[7];
        const int wkq = tid & 7;
#pragma unroll
        for (int u = 0; u < 6; u++) wn[u] = (tid + u * 256) >> 3;
        const bool w6v = tid < 64;
        wn[6] = (tid + 1536) >> 3;

        for (int pair = bid; pair < KSPLIT * mtiles; pair += NBLK) {
            const int ksb = pair % KSPLIT;
            const int mBase = (pair / KSPLIT) * GM_BM;
            const int k0 = ksb * KCHUNK;
            // warps whose entire 32-row strip is >= M have no useful work
            const bool wActive = (mBase + warpM * 32) < M;
            float4 pa0, pa1, pw[7];

            auto fetch = [&](int slab) {
                int g0 = mBase + arr0, g1 = mBase + arr1;
                pa0 = make_float4(0.f, 0.f, 0.f, 0.f);
                pa1 = make_float4(0.f, 0.f, 0.f, 0.f);
                const size_t kb = k0 + slab * 32 + akq * 4;
                if (g0 < M) pa0 = *reinterpret_cast<const float4*>(&g_A[(size_t)g0 * DD + kb]);
                if (g1 < M) pa1 = *reinterpret_cast<const float4*>(&g_A[(size_t)g1 * DD + kb]);
                const size_t kw = k0 + slab * 32 + wkq * 4;
#pragma unroll
                for (int u = 0; u < 6; u++)
                    pw[u] = *reinterpret_cast<const float4*>(&w1[(size_t)wn[u] * DD + kw]);
                if (w6v) pw[6] = *reinterpret_cast<const float4*>(&w1[(size_t)wn[6] * DD + kw]);
            };
            auto commit = [&]() {
                *reinterpret_cast<float4*>(&sA[arr0 * SASTR + akq * 4]) = pa0;
                *reinterpret_cast<float4*>(&sA[arr1 * SASTR + akq * 4]) = pa1;
#pragma unroll
                for (int u = 0; u < 6; u++)
                    *reinterpret_cast<float4*>(&sW[wn[u] * SASTR + wkq * 4]) = pw[u];
                if (w6v) *reinterpret_cast<float4*>(&sW[wn[6] * SASTR + wkq * 4]) = pw[6];
            };

            float acc[2][7][4];
#pragma unroll
            for (int f = 0; f < 2; f++)
#pragma unroll
                for (int i = 0; i < 7; i++)
#pragma unroll
                    for (int j = 0; j < 4; j++) acc[f][i][j] = 0.f;

            fetch(0);
            __syncthreads();   // prior iteration / phase done with sp
            commit();
            __syncthreads();

            for (int slab = 0; slab < NSLAB; slab++) {
                if (slab + 1 < NSLAB) fetch(slab + 1);
                if (wActive) {
#pragma unroll
                    for (int ks = 0; ks < 4; ks++) {
                        int kcol = ks * 8 + (lane & 3);
                        int row0 = warpM * 32 + (lane >> 2);
                        uint32_t a00 = __float_as_uint(sA[row0 * SASTR + kcol]);
                        uint32_t a01 = __float_as_uint(sA[(row0 + 8) * SASTR + kcol]);
                        uint32_t a02 = __float_as_uint(sA[row0 * SASTR + kcol + 4]);
                        uint32_t a03 = __float_as_uint(sA[(row0 + 8) * SASTR + kcol + 4]);
                        uint32_t a10 = __float_as_uint(sA[(row0 + 16) * SASTR + kcol]);
                        uint32_t a11 = __float_as_uint(sA[(row0 + 24) * SASTR + kcol]);
                        uint32_t a12 = __float_as_uint(sA[(row0 + 16) * SASTR + kcol + 4]);
                        uint32_t a13 = __float_as_uint(sA[(row0 + 24) * SASTR + kcol + 4]);
#pragma unroll
                        for (int nf = 0; nf < 7; nf++) {
                            if (nf < nfCnt) {
                                int n0 = (nfBase + nf) * 8 + (lane >> 2);
                                uint32_t b0 = __float_as_uint(sW[n0 * SASTR + kcol]);
                                uint32_t b1 = __float_as_uint(sW[n0 * SASTR + kcol + 4]);
                                mma_tf32(acc[0][nf][0], acc[0][nf][1], acc[0][nf][2], acc[0][nf][3],
                                         a00, a01, a02, a03, b0, b1);
                                mma_tf32(acc[1][nf][0], acc[1][nf][1], acc[1][nf][2], acc[1][nf][3],
                                         a10, a11, a12, a13, b0, b1);
                            }
                        }
                    }
                }
                if (slab + 1 < NSLAB) {
                    __syncthreads();
                    commit();
                    __syncthreads();
                }
            }
            if (wActive) {
#pragma unroll
                for (int f = 0; f < 2; f++) {
                    int rowA = mBase + warpM * 32 + f * 16 + (lane >> 2);
                    int rowB = rowA + 8;
#pragma unroll
                    for (int nf = 0; nf < 7; nf++) {
                        if (nf < nfCnt) {
                            int col = (nfBase + nf) * 8 + (lane & 3) * 2;
                            if (rowA < M)
                                *reinterpret_cast<float2*>(&g_P[((size_t)rowA * KSPLIT + ksb) * H1 + col]) =
                                    make_float2(acc[f][nf][0], acc[f][nf][1]);
                            if (rowB < M)
                                *reinterpret_cast<float2*>(&g_P[((size_t)rowB * KSPLIT + ksb) * H1 + col]) =
                                    make_float2(acc[f][nf][2], acc[f][nf][3]);
                        }
                    }
                }
            }
        }
    }
    grid_barrier(2);

    // ================= phase D: reduce + MLP =================
    {
        float* h1s = sp;
        float* h2s = sp + H1;
        for (int r = bid; r < M; r += NBLK) {
            __syncthreads();
            {
                const float* Pr = g_P + (size_t)r * KSPLIT * H1;
                if (tid < H1) {
                    float s = b1[tid];
#pragma unroll 14
                    for (int ks = 0; ks < KSPLIT; ks++)
                        s += Pr[ks * H1 + tid];
                    h1s[tid] = fmaxf(s, 0.f);
                }
            }
            __syncthreads();
            for (int j = wid; j < H2; j += 16) {
                int j2 = j + 8;
                bool v2 = j2 < H2;
                const float* wr0 = w2 + j * H1;
                const float* wr1 = w2 + (v2 ? j2 : j) * H1;
                float s0 = 0.f, s1 = 0.f;
#pragma unroll
                for (int k = lane; k < H1; k += 32) {
                    float hk = h1s[k];
                    s0 += wr0[k] * hk;
                    s1 += wr1[k] * hk;
                }
#pragma unroll
                for (int d = 16; d > 0; d >>= 1) {
                    s0 += __shfl_xor_sync(0xffffffffu, s0, d);
                    s1 += __shfl_xor_sync(0xffffffffu, s1, d);
                }
                if (lane == 0) {
                    h2s[j] = fmaxf(s0 + b2[j], 0.f);
                    if (v2) h2s[j2] = fmaxf(s1 + b2[j2], 0.f);
                }
            }
            __syncthreads();
            for (int q = wid; q < 85; q += 16) {
                int q2 = q + 8;
                bool v2 = q2 < 85;
                const float *wr0, *wr1;
                float bias0, bias1 = 0.f;
                if (q < KC) { wr0 = w3 + q * H2;        bias0 = b3[q]; }
                else        { wr0 = w4 + (q - KC) * H2; bias0 = b4[q - KC]; }
                if (v2) {
                    if (q2 < KC) { wr1 = w3 + q2 * H2;        bias1 = b3[q2]; }
                    else         { wr1 = w4 + (q2 - KC) * H2; bias1 = b4[q2 - KC]; }
                } else wr1 = wr0;
                float s0 = 0.f, s1 = 0.f;
#pragma unroll
                for (int k = lane; k < H2; k += 32) {
                    float hk = h2s[k];
                    s0 += wr0[k] * hk;
                    s1 += wr1[k] * hk;
                }
#pragma unroll
                for (int d = 16; d > 0; d >>= 1) {
                    s0 += __shfl_xor_sync(0xffffffffu, s0, d);
                    s1 += __shfl_xor_sync(0xffffffffu, s1, d);
                }
                if (lane == 0) {
                    g_out85[r * 85 + q] = s0 + bias0;
                    if (v2) g_out85[r * 85 + q2] = s1 + bias1;
                }
            }
        }
    }
    grid_barrier(3);

    // ================= phase E: scatter =================
    for (int idx = bid * NTHR + tid; idx < NTOT * 85; idx += NBLK * NTHR) {
        int bn = idx / 85;
        int q = idx % 85;
        int r = g_roiRow[bn];
        float val = g_out85[r * 85 + q];
        if (q < KC) {
            out[bn * KC + q] = val;                                        // z1
        } else {
            int k = (q - KC) / KC, cls = (q - KC) % KC;
            int b = bn / NROI, n = bn % NROI;
            out[NTOT * KC + (((b * 4 + k) * NROI + n) * KC + cls)] = val;  // z3
        }
    }
}

// ---------------- launch ----------------
extern "C" void kernel_launch(void* const* d_in, const int* in_sizes, int n_in,
                              void* d_out, int out_size) {
    const float* cfeats = (const float*)d_in[0];
    const float* regcls = (const float*)d_in[1];
    const float* wan    = (const float*)d_in[2];
    const float* han    = (const float*)d_in[3];
    const float* xan    = (const float*)d_in[4];
    const float* yan    = (const float*)d_in[5];
    const float* w1     = (const float*)d_in[6];
    const float* b1     = (const float*)d_in[7];
    const float* w2     = (const float*)d_in[8];
    const float* b2     = (const float*)d_in[9];
    const float* w3     = (const float*)d_in[10];
    const float* b3     = (const float*)d_in[11];
    const float* w4     = (const float*)d_in[12];
    const float* b4     = (const float*)d_in[13];
    float* out = (float*)d_out;

    mega_kernel<<<NBLK, NTHR>>>(cfeats, regcls, wan, han, xan, yan,
                                w1, b1, w2, b2, w3, b3, w4, b4, out);
}